// round 10
// baseline (speedup 1.0000x reference)
#include <cuda_runtime.h>
#include <cuda_bf16.h>
#include <cstdint>

// LinearMPC via mma.sync bf16 (split hi/lo), cluster-of-16 u-exchange.
// u <- clip(u - s*(uH + f)), 100 iters, B=2048, M=512, H symmetric.
// R10: NC=32 per CTA -> 105KB smem -> 2 CTAs/SM (4 warps/SMSP).

#define MD 512
#define BATCH 2048
#define ITERS 100
#define STEPC 0.01f
#define CLS 16
#define CB 128
#define NC 32
#define KC 32
#define NCHUNK 16
#define THREADS 256
#define HSTR 1040u        // H smem row stride (1024 + 16)
#define ASTR 80u          // u-chunk row stride (64 + 16)
#define SM_HH 0u
#define SM_HL 33280u      // 32*HSTR
#define SM_U  66560u
#define UPLANE 10240u     // 128*ASTR
#define UBUF   20480u     // hi+lo planes
#define SMEM_TOTAL 107520 // SM_U + 2*UBUF

__device__ __align__(16) float         g_f [BATCH * MD];
__device__ __align__(16) __nv_bfloat16 g_uh[BATCH * MD];
__device__ __align__(16) __nv_bfloat16 g_ul[BATCH * MD];

__device__ __forceinline__ uint32_t smem_u32_of(const void* p) {
    uint32_t a;
    asm("{ .reg .u64 t; cvta.to.shared.u64 t, %1; cvt.u32.u64 %0, t; }"
        : "=r"(a) : "l"(p));
    return a;
}
__device__ __forceinline__ void ldm_x4(uint32_t* r, uint32_t addr) {
    asm volatile(
        "ldmatrix.sync.aligned.m8n8.x4.shared.b16 {%0,%1,%2,%3}, [%4];"
        : "=r"(r[0]), "=r"(r[1]), "=r"(r[2]), "=r"(r[3]) : "r"(addr));
}
__device__ __forceinline__ void cp16(uint32_t s, const void* g) {
    asm volatile("cp.async.cg.shared.global [%0], [%1], 16;" :: "r"(s), "l"(g));
}
__device__ __forceinline__ void cp_commit() {
    asm volatile("cp.async.commit_group;");
}
template <int N>
__device__ __forceinline__ void cp_wait() {
    asm volatile("cp.async.wait_group %0;" :: "n"(N));
}
__device__ __forceinline__ void cluster_sync() {
    asm volatile("barrier.cluster.arrive.aligned;" ::: "memory");  // release
    asm volatile("barrier.cluster.wait.aligned;" ::: "memory");    // acquire
}
__device__ __forceinline__ void mma4(float* d, const uint32_t* a,
                                     const uint32_t* b) {
    asm volatile(
        "mma.sync.aligned.m16n8k16.row.col.f32.bf16.bf16.f32 "
        "{%0,%1,%2,%3}, {%4,%5,%6,%7}, {%8,%9}, {%0,%1,%2,%3};"
        : "+f"(d[0]), "+f"(d[1]), "+f"(d[2]), "+f"(d[3])
        : "r"(a[0]), "r"(a[1]), "r"(a[2]), "r"(a[3]), "r"(b[0]), "r"(b[1]));
}
__device__ __forceinline__ uint32_t bfsplit_hi(float x, float& r) {
    __nv_bfloat16 h = __float2bfloat16(x);
    r = x - __bfloat162float(h);
    return (uint32_t)__bfloat16_as_ushort(h);
}
__device__ __forceinline__ float clamp1(float x) {
    return fminf(fmaxf(x, -1.0f), 1.0f);
}
__device__ __forceinline__ void split_store(float v0, float v1,
                                            __nv_bfloat16* ph,
                                            __nv_bfloat16* pl) {
    float q0, q1, z;
    uint32_t a0 = bfsplit_hi(v0, q0), a1 = bfsplit_hi(v1, q1);
    __stcg((uint32_t*)ph, a0 | (a1 << 16));
    __stcg((uint32_t*)pl, bfsplit_hi(q0, z) | (bfsplit_hi(q1, z) << 16));
}

// Prologue: f[b, k*8+i] = -2 * Phi[k] @ Q @ (xref[b,k] - xref[b,0])
__global__ void mpc_f_kernel(const float* __restrict__ xref,
                             const float* __restrict__ Phi,
                             const float* __restrict__ Q) {
    int b = blockIdx.x, k = threadIdx.x;
    const float* xr = xref + (size_t)b * 65 * 8;
    float dx[8], t[8];
#pragma unroll
    for (int l = 0; l < 8; l++) dx[l] = xr[k * 8 + l] - xr[l];
#pragma unroll
    for (int j = 0; j < 8; j++) {
        float s = 0.f;
#pragma unroll
        for (int l = 0; l < 8; l++) s = fmaf(Q[j * 8 + l], dx[l], s);
        t[j] = s;
    }
    const float* Pk = Phi + (size_t)k * 64;
#pragma unroll
    for (int i = 0; i < 8; i++) {
        float s = 0.f;
#pragma unroll
        for (int j = 0; j < 8; j++) s = fmaf(Pk[i * 8 + j], t[j], s);
        g_f[(size_t)b * MD + k * 8 + i] = -2.0f * s;
    }
}

__global__ void __launch_bounds__(THREADS, 2)
mpc_mma_kernel(const float* __restrict__ Hm, float* __restrict__ out) {
    extern __shared__ char smem[];
    const uint32_t sb = smem_u32_of(smem);
    const int tid = threadIdx.x, lane = tid & 31;
    const int qr = lane >> 2, qc = lane & 3;
    const int w = tid >> 5, wm = w & 3, wn = w >> 2;   // 4 m-groups x 2 n-groups
    uint32_t rank;
    asm("mov.u32 %0, %%cluster_ctarank;" : "=r"(rank));
    const int cbase = (int)(blockIdx.x / CLS) * CB;
    const int n0 = (int)rank * NC;

    // ---- Stage H rows [n0, n0+32) as bf16 hi/lo (resident all iterations).
    for (int i = tid * 4; i < NC * MD; i += THREADS * 4) {
        int n = i >> 9, k = i & (MD - 1);
        float4 h = *(const float4*)&Hm[(size_t)(n0 + n) * MD + k];
        float r0, r1, r2, r3, z;
        uint32_t h0 = bfsplit_hi(h.x, r0), h1 = bfsplit_hi(h.y, r1);
        uint32_t h2 = bfsplit_hi(h.z, r2), h3 = bfsplit_hi(h.w, r3);
        uint32_t l0 = bfsplit_hi(r0, z), l1 = bfsplit_hi(r1, z);
        uint32_t l2 = bfsplit_hi(r2, z), l3 = bfsplit_hi(r3, z);
        uint32_t off = (uint32_t)n * HSTR + (uint32_t)(k << 1);
        *(uint2*)(smem + SM_HH + off) = make_uint2(h0 | (h1 << 16), h2 | (h3 << 16));
        *(uint2*)(smem + SM_HL + off) = make_uint2(l0 | (l1 << 16), l2 | (l3 << 16));
    }

    // ---- ldmatrix per-lane base addresses (formulas validated R8/R9).
    uint32_t aBase[2], bBase;
#pragma unroll
    for (int mf = 0; mf < 2; mf++) {
        int row = 32 * wm + 16 * mf + (lane & 7) + 8 * ((lane >> 3) & 1);
        aBase[mf] = sb + SM_U + (uint32_t)row * ASTR + 16u * (lane >> 4);
    }
    {
        int row = 16 * wn + 8 * (lane >> 4) + (lane & 7);
        bBase = sb + (uint32_t)row * HSTR + 16u * ((lane >> 3) & 1);
    }

    // ---- Loader geometry: thread -> (row = tid/2, plane = tid&1), 64B/chunk.
    const int lrow = tid >> 1, plane = tid & 1;
    const __nv_bfloat16* lsrc =
        (plane ? g_ul : g_uh) + (size_t)(cbase + lrow) * MD;
    const uint32_t ldst = sb + SM_U + (uint32_t)plane * UPLANE
                          + (uint32_t)lrow * ASTR;

    // ---- Per-thread fragment state: fs = s*f, u master.
    const int colb = n0 + 16 * wn + 2 * qc;
    float fsv[2][2][4], u_m[2][2][4];
#pragma unroll
    for (int mf = 0; mf < 2; mf++) {
        int r0 = cbase + 32 * wm + 16 * mf + qr;
#pragma unroll
        for (int nf = 0; nf < 2; nf++) {
            float2 a = *(const float2*)&g_f[(size_t)r0 * MD + colb + 8 * nf];
            float2 b = *(const float2*)&g_f[(size_t)(r0 + 8) * MD + colb + 8 * nf];
            fsv[mf][nf][0] = STEPC * a.x;  fsv[mf][nf][1] = STEPC * a.y;
            fsv[mf][nf][2] = STEPC * b.x;  fsv[mf][nf][3] = STEPC * b.y;
#pragma unroll
            for (int c = 0; c < 4; c++)
                u_m[mf][nf][c] = clamp1(-fsv[mf][nf][c]);
        }
    }
    // Store u1 (bf16 hi/lo) for the exchange.
#pragma unroll
    for (int mf = 0; mf < 2; mf++) {
        int r0 = cbase + 32 * wm + 16 * mf + qr;
#pragma unroll
        for (int nf = 0; nf < 2; nf++) {
            size_t o0 = (size_t)r0 * MD + colb + 8 * nf;
            size_t o8 = (size_t)(r0 + 8) * MD + colb + 8 * nf;
            split_store(u_m[mf][nf][0], u_m[mf][nf][1], &g_uh[o0], &g_ul[o0]);
            split_store(u_m[mf][nf][2], u_m[mf][nf][3], &g_uh[o8], &g_ul[o8]);
        }
    }
    __syncthreads();

    for (int it = 1; it < ITERS; it++) {
        cluster_sync();   // release/acquire: u stores visible cluster-wide

        // Prime 2 chunks.
#pragma unroll
        for (int pc = 0; pc < 2; pc++) {
            uint32_t d = ldst + (uint32_t)pc * UBUF;
            const __nv_bfloat16* g = lsrc + pc * KC;
            cp16(d, g); cp16(d + 16, g + 8);
            cp16(d + 32, g + 16); cp16(d + 48, g + 24);
            cp_commit();
        }

        float acc[2][2][4];
#pragma unroll
        for (int mf = 0; mf < 2; mf++)
#pragma unroll
            for (int nf = 0; nf < 2; nf++)
#pragma unroll
                for (int c = 0; c < 4; c++) acc[mf][nf][c] = 0.f;

#pragma unroll 1
        for (int kc = 0; kc < NCHUNK; kc++) {
            if (kc == NCHUNK - 1) cp_wait<0>(); else cp_wait<1>();
            __syncthreads();   // chunk kc data visible to all

            const uint32_t abuf = (uint32_t)(kc & 1) * UBUF;
            const uint32_t bko = (uint32_t)kc * 64u;
#pragma unroll
            for (int ks = 0; ks < 2; ks++) {
                uint32_t ah[2][4], al[2][4], bh[4], bl[4];
                ldm_x4(ah[0], aBase[0] + abuf + ks * 32);
                ldm_x4(ah[1], aBase[1] + abuf + ks * 32);
                ldm_x4(al[0], aBase[0] + abuf + UPLANE + ks * 32);
                ldm_x4(al[1], aBase[1] + abuf + UPLANE + ks * 32);
                ldm_x4(bh, bBase + bko + ks * 32);
                ldm_x4(bl, bBase + SM_HL + bko + ks * 32);
#pragma unroll
                for (int nf = 0; nf < 2; nf++) {
                    const uint32_t* Bh = &bh[nf * 2];
                    const uint32_t* Bl = &bl[nf * 2];
#pragma unroll
                    for (int mf = 0; mf < 2; mf++) {
                        mma4(acc[mf][nf], ah[mf], Bh);
                        mma4(acc[mf][nf], al[mf], Bh);
                        mma4(acc[mf][nf], ah[mf], Bl);
                    }
                }
            }
            __syncthreads();   // all warps done with buffer kc&1
            if (kc + 2 < NCHUNK) {
                uint32_t d = ldst + (uint32_t)(kc & 1) * UBUF;
                const __nv_bfloat16* g = lsrc + (kc + 2) * KC;
                cp16(d, g); cp16(d + 16, g + 8);
                cp16(d + 32, g + 16); cp16(d + 48, g + 24);
                cp_commit();
            }
        }

        // ---- u <- clip(u - s*acc - fs); store bf16 hi/lo (fp32 out on last).
        const bool last = (it == ITERS - 1);
#pragma unroll
        for (int mf = 0; mf < 2; mf++) {
            int r0 = cbase + 32 * wm + 16 * mf + qr;
#pragma unroll
            for (int nf = 0; nf < 2; nf++) {
#pragma unroll
                for (int c = 0; c < 4; c++) {
                    float t = fmaf(-STEPC, acc[mf][nf][c], u_m[mf][nf][c])
                              - fsv[mf][nf][c];
                    u_m[mf][nf][c] = clamp1(t);
                }
                size_t o0 = (size_t)r0 * MD + colb + 8 * nf;
                size_t o8 = (size_t)(r0 + 8) * MD + colb + 8 * nf;
                if (last) {
                    *(float2*)&out[o0] = make_float2(u_m[mf][nf][0], u_m[mf][nf][1]);
                    *(float2*)&out[o8] = make_float2(u_m[mf][nf][2], u_m[mf][nf][3]);
                } else {
                    split_store(u_m[mf][nf][0], u_m[mf][nf][1], &g_uh[o0], &g_ul[o0]);
                    split_store(u_m[mf][nf][2], u_m[mf][nf][3], &g_uh[o8], &g_ul[o8]);
                }
            }
        }
    }
}

extern "C" void kernel_launch(void* const* d_in, const int* in_sizes, int n_in,
                              void* d_out, int out_size) {
    // metadata order: x0, xref, H, Phi, Q
    const float* xref = (const float*)d_in[1];
    const float* H    = (const float*)d_in[2];
    const float* Phi  = (const float*)d_in[3];
    const float* Q    = (const float*)d_in[4];
    float* out        = (float*)d_out;

    cudaFuncSetAttribute(mpc_mma_kernel,
                         cudaFuncAttributeMaxDynamicSharedMemorySize, SMEM_TOTAL);
    cudaFuncSetAttribute(mpc_mma_kernel,
                         cudaFuncAttributeNonPortableClusterSizeAllowed, 1);

    mpc_f_kernel<<<BATCH, 64>>>(xref, Phi, Q);

    cudaLaunchConfig_t cfg = {};
    cfg.gridDim = dim3((BATCH / CB) * CLS, 1, 1);   // 256 CTAs
    cfg.blockDim = dim3(THREADS, 1, 1);
    cfg.dynamicSmemBytes = SMEM_TOTAL;
    cudaLaunchAttribute attrs[1];
    attrs[0].id = cudaLaunchAttributeClusterDimension;
    attrs[0].val.clusterDim.x = CLS;
    attrs[0].val.clusterDim.y = 1;
    attrs[0].val.clusterDim.z = 1;
    cfg.attrs = attrs;
    cfg.numAttrs = 1;
    cudaLaunchKernelEx(&cfg, mpc_mma_kernel, H, out);
}

// round 11
// speedup vs baseline: 2.0524x; 2.0524x over previous
#include <cuda_runtime.h>
#include <cuda_bf16.h>
#include <cstdint>

// LinearMPC via mma.sync bf16 split hi/lo — CTA-local, no clusters, no cp.async.
// u <- clip(u - s*(uH + f)), 100 iters, B=2048, M=512, H symmetric.
// CTA = 16 batches x full M=512. H streamed L2->regs via LDG.64 (packed hi|lo
// words, PRMT decode), register double-buffered. u packed in SMEM only.

#define MD 512
#define BATCH 2048
#define BT 16
#define ITERS 100
#define STEPC 0.01f
#define THREADS 256
#define USTR 2080u            // u_s / f_s row stride bytes (520 words)
#define F_OFF 33280u          // f_s offset = 16*USTR
#define SMEM_TOTAL 66560

__device__ __align__(16) float    g_f [BATCH * MD];
__device__ __align__(16) uint32_t g_hp[MD * MD];     // (bf16hi<<16)|bf16lo

__device__ __forceinline__ uint32_t prmt(uint32_t a, uint32_t b, uint32_t s) {
    uint32_t d;
    asm("prmt.b32 %0, %1, %2, %3;" : "=r"(d) : "r"(a), "r"(b), "r"(s));
    return d;
}
__device__ __forceinline__ void mma4(float* d, const uint32_t* a,
                                     const uint32_t* b) {
    asm volatile(
        "mma.sync.aligned.m16n8k16.row.col.f32.bf16.bf16.f32 "
        "{%0,%1,%2,%3}, {%4,%5,%6,%7}, {%8,%9}, {%0,%1,%2,%3};"
        : "+f"(d[0]), "+f"(d[1]), "+f"(d[2]), "+f"(d[3])
        : "r"(a[0]), "r"(a[1]), "r"(a[2]), "r"(a[3]), "r"(b[0]), "r"(b[1]));
}
__device__ __forceinline__ float clamp1(float x) {
    return fminf(fmaxf(x, -1.0f), 1.0f);
}
__device__ __forceinline__ uint32_t pack_u(float v) {
    __nv_bfloat16 h = __float2bfloat16(v);
    __nv_bfloat16 l = __float2bfloat16(v - __bfloat162float(h));
    return ((uint32_t)__bfloat16_as_ushort(h) << 16)
         | (uint32_t)__bfloat16_as_ushort(l);
}
__device__ __forceinline__ float dec(uint32_t w) {
    return __bfloat162float(__ushort_as_bfloat16((unsigned short)(w >> 16)))
         + __bfloat162float(__ushort_as_bfloat16((unsigned short)(w & 0xFFFFu)));
}

// Prologue 1: f[b, k*8+i] = -2 * Phi[k] @ Q @ (xref[b,k] - xref[b,0])
__global__ void mpc_f_kernel(const float* __restrict__ xref,
                             const float* __restrict__ Phi,
                             const float* __restrict__ Q) {
    int b = blockIdx.x, k = threadIdx.x;
    const float* xr = xref + (size_t)b * 65 * 8;
    float dx[8], t[8];
#pragma unroll
    for (int l = 0; l < 8; l++) dx[l] = xr[k * 8 + l] - xr[l];
#pragma unroll
    for (int j = 0; j < 8; j++) {
        float s = 0.f;
#pragma unroll
        for (int l = 0; l < 8; l++) s = fmaf(Q[j * 8 + l], dx[l], s);
        t[j] = s;
    }
    const float* Pk = Phi + (size_t)k * 64;
#pragma unroll
    for (int i = 0; i < 8; i++) {
        float s = 0.f;
#pragma unroll
        for (int j = 0; j < 8; j++) s = fmaf(Pk[i * 8 + j], t[j], s);
        g_f[(size_t)b * MD + k * 8 + i] = -2.0f * s;
    }
}

// Prologue 2: pack H fp32 -> (bf16hi<<16)|bf16lo words.
__global__ void mpc_hpack_kernel(const float* __restrict__ Hm) {
    int i = blockIdx.x * 256 + threadIdx.x;
    float v = Hm[i];
    g_hp[i] = pack_u(v);
}

// B-fragment prefetch for one 16-k chunk into register buffer BUF[8][2].
#define PREFETCH(BUF, KC_)                                                    \
    {                                                                         \
        const uint2* hp_ = (const uint2*)(g_hp + hbase0 +                     \
                                          (uint32_t)(((KC_) & 31) * 16));     \
        _Pragma("unroll")                                                     \
        for (int mf_ = 0; mf_ < 8; mf_++) {                                   \
            BUF[mf_][0] = __ldg(hp_ + mf_ * 2048);                            \
            BUF[mf_][1] = __ldg(hp_ + mf_ * 2048 + 4);                        \
        }                                                                     \
    }

// MMA for one 16-k chunk: A (u) from packed SMEM, B from register buffer.
#define COMPUTE(BUF, KC_)                                                     \
    {                                                                         \
        const uint32_t ub_ = uAb + (uint32_t)((KC_) & 31) * 64u;              \
        uint2 wa0 = *(const uint2*)(smem + ub_);                              \
        uint2 wa2 = *(const uint2*)(smem + ub_ + 32u);                        \
        uint2 wa1 = *(const uint2*)(smem + ub_ + 8u * USTR);                  \
        uint2 wa3 = *(const uint2*)(smem + ub_ + 8u * USTR + 32u);            \
        uint32_t ah[4], al[4];                                                \
        ah[0] = prmt(wa0.x, wa0.y, 0x7632u); al[0] = prmt(wa0.x, wa0.y, 0x5410u); \
        ah[1] = prmt(wa1.x, wa1.y, 0x7632u); al[1] = prmt(wa1.x, wa1.y, 0x5410u); \
        ah[2] = prmt(wa2.x, wa2.y, 0x7632u); al[2] = prmt(wa2.x, wa2.y, 0x5410u); \
        ah[3] = prmt(wa3.x, wa3.y, 0x7632u); al[3] = prmt(wa3.x, wa3.y, 0x5410u); \
        _Pragma("unroll")                                                     \
        for (int mf_ = 0; mf_ < 8; mf_++) {                                   \
            uint32_t bh[2], bl[2];                                            \
            bh[0] = prmt(BUF[mf_][0].x, BUF[mf_][0].y, 0x7632u);              \
            bl[0] = prmt(BUF[mf_][0].x, BUF[mf_][0].y, 0x5410u);              \
            bh[1] = prmt(BUF[mf_][1].x, BUF[mf_][1].y, 0x7632u);              \
            bl[1] = prmt(BUF[mf_][1].x, BUF[mf_][1].y, 0x5410u);              \
            mma4(acc[mf_], ah, bh);                                           \
            mma4(acc[mf_], al, bh);                                           \
            mma4(acc[mf_], ah, bl);                                           \
        }                                                                     \
    }

__global__ void __launch_bounds__(THREADS, 1)
mpc_mma_kernel(float* __restrict__ out) {
    extern __shared__ char smem[];   // u_s [16][520w] @0; f_s [16][520f] @F_OFF
    const int tid = threadIdx.x, lane = tid & 31;
    const int qr = lane >> 2, qc = lane & 3;
    const int w = tid >> 5;
    const int m0w = w * 64;                 // warp's 64-wide m-slice
    const int cb = blockIdx.x * BT;

    // Stage f.
    for (int i = tid; i < BT * MD; i += THREADS) {
        int b = i >> 9, m = i & (MD - 1);
        *(float*)(smem + F_OFF + (uint32_t)b * USTR + (uint32_t)m * 4u) =
            g_f[(size_t)(cb + b) * MD + m];
    }
    __syncthreads();

    // Iteration 0: u1 = clip(-s*f), write packed u_s.
#pragma unroll
    for (int mf = 0; mf < 8; mf++) {
        int mcol = m0w + 8 * mf + 2 * qc;
        float2 f0 = *(float2*)(smem + F_OFF + (uint32_t)qr * USTR + mcol * 4);
        float2 f1 = *(float2*)(smem + F_OFF + (uint32_t)(qr + 8) * USTR + mcol * 4);
        *(uint2*)(smem + (uint32_t)qr * USTR + mcol * 4) =
            make_uint2(pack_u(clamp1(-STEPC * f0.x)), pack_u(clamp1(-STEPC * f0.y)));
        *(uint2*)(smem + (uint32_t)(qr + 8) * USTR + mcol * 4) =
            make_uint2(pack_u(clamp1(-STEPC * f1.x)), pack_u(clamp1(-STEPC * f1.y)));
    }
    __syncthreads();

    // Per-lane constant offsets.
    const uint32_t hbase0 = (uint32_t)(m0w + qr) * 512u + 2u * qc;   // word idx
    const uint32_t uAb = (uint32_t)qr * USTR + 8u * qc;              // byte

    uint2 B0[8][2], B1[8][2];
    PREFETCH(B0, 0);
    PREFETCH(B1, 1);

    for (int it = 1; it < ITERS; it++) {
        float acc[8][4];
#pragma unroll
        for (int mf = 0; mf < 8; mf++) {
            int mcol = m0w + 8 * mf + 2 * qc;
            float2 f0 = *(float2*)(smem + F_OFF + (uint32_t)qr * USTR + mcol * 4);
            float2 f1 = *(float2*)(smem + F_OFF + (uint32_t)(qr + 8) * USTR + mcol * 4);
            acc[mf][0] = f0.x; acc[mf][1] = f0.y;
            acc[mf][2] = f1.x; acc[mf][3] = f1.y;
        }

#pragma unroll 1
        for (int kc = 0; kc < 32; kc += 2) {
            COMPUTE(B0, kc);
            PREFETCH(B0, kc + 2);     // wraps: prefetches next iter's chunk 0/1
            COMPUTE(B1, kc + 1);
            PREFETCH(B1, kc + 3);
        }

        __syncthreads();   // all warps done reading u_s this iteration

        const bool last = (it == ITERS - 1);
#pragma unroll
        for (int mf = 0; mf < 8; mf++) {
            int mcol = m0w + 8 * mf + 2 * qc;
            uint2 w0 = *(uint2*)(smem + (uint32_t)qr * USTR + mcol * 4);
            uint2 w1 = *(uint2*)(smem + (uint32_t)(qr + 8) * USTR + mcol * 4);
            float v0 = clamp1(fmaf(-STEPC, acc[mf][0], dec(w0.x)));
            float v1 = clamp1(fmaf(-STEPC, acc[mf][1], dec(w0.y)));
            float v2 = clamp1(fmaf(-STEPC, acc[mf][2], dec(w1.x)));
            float v3 = clamp1(fmaf(-STEPC, acc[mf][3], dec(w1.y)));
            if (last) {
                *(float2*)&out[(size_t)(cb + qr) * MD + mcol] = make_float2(v0, v1);
                *(float2*)&out[(size_t)(cb + qr + 8) * MD + mcol] = make_float2(v2, v3);
            } else {
                *(uint2*)(smem + (uint32_t)qr * USTR + mcol * 4) =
                    make_uint2(pack_u(v0), pack_u(v1));
                *(uint2*)(smem + (uint32_t)(qr + 8) * USTR + mcol * 4) =
                    make_uint2(pack_u(v2), pack_u(v3));
            }
        }
        __syncthreads();   // u_s update visible before next iteration's reads
    }
}

extern "C" void kernel_launch(void* const* d_in, const int* in_sizes, int n_in,
                              void* d_out, int out_size) {
    // metadata order: x0, xref, H, Phi, Q
    const float* xref = (const float*)d_in[1];
    const float* H    = (const float*)d_in[2];
    const float* Phi  = (const float*)d_in[3];
    const float* Q    = (const float*)d_in[4];
    float* out        = (float*)d_out;

    cudaFuncSetAttribute(mpc_mma_kernel,
                         cudaFuncAttributeMaxDynamicSharedMemorySize, SMEM_TOTAL);

    mpc_f_kernel<<<BATCH, 64>>>(xref, Phi, Q);
    mpc_hpack_kernel<<<MD * MD / 256, 256>>>(H);
    mpc_mma_kernel<<<BATCH / BT, THREADS, SMEM_TOTAL>>>(out);
}